// round 10
// baseline (speedup 1.0000x reference)
#include <cuda_runtime.h>

#define NJ   17
#define NP   14
#define NB   256
#define NCH  59            // 17 + 3*14
#define GX   (NJ + NP)     // 31 block columns
#define NBLK (GX * NB)     // 7936 blocks

__constant__ int c_par[NP] = {0,1,2,0,4,5,0,8,14,15,8,11,12,8};
__constant__ int c_chi[NP] = {1,2,3,4,5,6,8,14,15,16,11,12,13,10};

// Per-column accumulators (L2 atomics only). Zero at module load; the last
// block re-zeroes them after reading, so every launch starts from zero.
__device__ double       g_slot[GX];
__device__ unsigned int g_count;

// max of exp(-(i-x)^2/4) over integer grid i in [0,63]: nearest grid point.
__device__ __forceinline__ float gmax1d(float x) {
    float i = fminf(fmaxf(rintf(x), 0.f), 63.f);
    float d = i - x;
    return __expf(-d * d * 0.25f);
}

__device__ __forceinline__ float blockReduce256(float v, float* red, int tid) {
    #pragma unroll
    for (int o = 16; o > 0; o >>= 1) v += __shfl_down_sync(0xffffffffu, v, o);
    if ((tid & 31) == 0) red[tid >> 5] = v;
    __syncthreads();
    v = (tid < 8) ? red[tid] : 0.f;
    if (tid < 32) {
        #pragma unroll
        for (int o = 4; o > 0; o >>= 1) v += __shfl_down_sync(0xffffffffu, v, o);
    }
    return v;   // valid on tid 0
}

__global__ void k_fused(const float* __restrict__ mo,
                        const float* __restrict__ joints,
                        const float* __restrict__ j2d,
                        const float* __restrict__ pred,
                        float* __restrict__ out) {
    __shared__ __align__(16) float ex[64], ey[64], ex2[64], ey2[64];
    __shared__ float red[8];
    __shared__ int   s_last;

    const int b   = blockIdx.y;
    const int tid = threadIdx.x;

    const float4* ey4  = (const float4*)ey;
    const float4* ey24 = (const float4*)ey2;

    if (blockIdx.x < NJ) {
        // ---------------- L2D path ----------------
        const int j = blockIdx.x;
        const float x = j2d[(b * NJ + j) * 2 + 0] * 64.f;
        const float y = j2d[(b * NJ + j) * 2 + 1] * 64.f;
        const float inv = 1.f / (gmax1d(x) * gmax1d(y));
        if (tid < 64)       { float d = (float)tid - x;        ex[tid] = expf(-d * d * 0.25f) * inv; }
        else if (tid < 128) { int k = tid - 64; float d = (float)k - y; ey[k] = expf(-d * d * 0.25f); }
        __syncthreads();

        const float4* p = (const float4*)(mo + (((size_t)b * NCH + j) << 12));
        float acc = 0.f;
        #pragma unroll
        for (int it = 0; it < 4; it++) {
            int e4 = tid + it * 256;
            float4 m = p[e4];
            int i  = e4 >> 4;
            int k4 = e4 & 15;
            float  hx = ex[i];
            float4 v  = ey4[k4];
            float d0 = m.x - hx * v.x;
            float d1 = m.y - hx * v.y;
            float d2 = m.z - hx * v.z;
            float d3 = m.w - hx * v.w;
            acc += d0 * d0 + d1 * d1 + d2 * d2 + d3 * d3;
        }
        float S = blockReduce256(acc, red, tid);
        if (tid == 0) atomicAdd(&g_slot[blockIdx.x], (double)S);
    } else {
        // ---------------- HEM path ----------------
        const int pr = blockIdx.x - NJ;
        const int pj = c_par[pr], cj = c_chi[pr];
        const float xp = j2d[(b * NJ + pj) * 2 + 0] * 64.f;
        const float yp = j2d[(b * NJ + pj) * 2 + 1] * 64.f;
        const float xc = j2d[(b * NJ + cj) * 2 + 0] * 64.f;
        const float yc = j2d[(b * NJ + cj) * 2 + 1] * 64.f;
        const float invp = 1.f / (gmax1d(xp) * gmax1d(yp));
        const float invc = 1.f / (gmax1d(xc) * gmax1d(yc));
        if (tid < 64)       { float d = (float)tid - xp;         ex [tid] = expf(-d * d * 0.25f) * invp; }
        else if (tid < 128) { int k = tid - 64;  float d = (float)k - yp; ey [k] = expf(-d * d * 0.25f); }
        else if (tid < 192) { int k = tid - 128; float d = (float)k - xc; ex2[k] = expf(-d * d * 0.25f) * invc; }
        else                { int k = tid - 192; float d = (float)k - yc; ey2[k] = expf(-d * d * 0.25f); }
        __syncthreads();

        const float dz = joints[(b * NJ + pj) * 3 + 2] - joints[(b * NJ + cj) * 3 + 2];
        const int r = (dz > 0.1f) ? 1 : ((fabsf(dz) < 0.1f) ? 0 : -1);

        const float4* p0 = (const float4*)(mo + (((size_t)b * NCH + NJ + pr * 3) << 12));
        float a0 = 0.f, a1 = 0.f, a2 = 0.f;
        #pragma unroll
        for (int it = 0; it < 4; it++) {
            int e4 = tid + it * 256;
            int i  = e4 >> 4;
            int k4 = e4 & 15;
            float  hpx = ex[i];
            float  hcx = ex2[i];
            float4 vp  = ey4[k4];
            float4 vc  = ey24[k4];
            float m0[4], m1[4], m2[4];
            *(float4*)m0 = p0[e4];
            *(float4*)m1 = p0[e4 + 1024];
            *(float4*)m2 = p0[e4 + 2048];
            #pragma unroll
            for (int n = 0; n < 4; n++) {
                float hp = hpx * (&vp.x)[n];
                float hc = hcx * (&vc.x)[n];
                float t0 = (r == -1) ? hc : 0.f;
                float t1 = (r ==  0) ? (hp + hc) : hp;
                float t2 = (r ==  1) ? hc : 0.f;
                float d0 = t0 - m0[n];
                float d1 = t1 - m1[n];
                float d2 = t2 - m2[n];
                a0 += d0 * d0;
                a1 += d1 * d1;
                a2 += d2 * d2;
            }
        }
        float S0 = blockReduce256(a0, red, tid);
        __syncthreads();
        float S1 = blockReduce256(a1, red, tid);
        __syncthreads();
        float S2 = blockReduce256(a2, red, tid);
        if (tid == 0) {
            float s = sqrtf(S0) + sqrtf(S1) + sqrtf(S2);
            atomicAdd(&g_slot[blockIdx.x], (double)(s * s));
        }
    }

    // ---- last-block detection: release-ordered counter (NO threadfence/L1 flush) ----
    if (tid == 0) {
        unsigned int prev;
        asm volatile("atom.add.release.gpu.u32 %0, [%1], 1;"
                     : "=r"(prev) : "l"(&g_count) : "memory");
        s_last = (prev == (unsigned)(NBLK - 1)) ? 1 : 0;
    }
    __syncthreads();
    if (!s_last) return;

    // ---- last block only: acquire, combine, l3d, output, reset ----
    asm volatile("fence.acquire.gpu;" ::: "memory");

    // l3d: thread tid = batch tid (51 abs-diffs)
    float l = 0.f;
    const float* jb = joints + tid * NJ * 3;
    const float* pb = pred   + tid * NJ * 3;
    #pragma unroll
    for (int i = 0; i < NJ * 3; i++) l += fabsf(jb[i] - pb[i]);
    __syncthreads();   // red[] reuse
    float ltot = blockReduce256(l, red, tid);

    if (tid == 0) {
        double s = 0.0;
        #pragma unroll
        for (int i = 0; i < GX; i++) s += __ldcg(&g_slot[i]);
        out[0] = (float)(((double)ltot + 0.005 * s) * (1.0 / 256.0));
        g_count = 0;
    }
    if (tid < GX) g_slot[tid] = 0.0;   // reset for next graph replay
}

extern "C" void kernel_launch(void* const* d_in, const int* in_sizes, int n_in,
                              void* d_out, int out_size) {
    const float* pred   = (const float*)d_in[0];
    const float* joints = (const float*)d_in[1];
    const float* mo     = (const float*)d_in[2];
    const float* j2d    = (const float*)d_in[3];
    float* out = (float*)d_out;

    k_fused<<<dim3(GX, NB), 256>>>(mo, joints, j2d, pred, out);
}

// round 11
// speedup vs baseline: 1.2051x; 1.2051x over previous
#include <cuda_runtime.h>

#define NJ   17
#define NP   14
#define NB   256
#define NCH  59            // 17 + 3*14
#define GX   (NJ + NP)     // 31 block columns
#define NBLK (GX * NB)     // 7936 blocks
#define NSLOT (GX + 1)     // 31 loss slots + 1 l3d slot

__constant__ int c_par[NP] = {0,1,2,0,4,5,0,8,14,15,8,11,12,8};
__constant__ int c_chi[NP] = {1,2,3,4,5,6,8,14,15,16,11,12,13,10};

// Accumulators (L2 atomics only). Zero at module load; the last block
// re-zeroes them after reading, so every launch starts from zero.
__device__ double       g_slot[NSLOT];
__device__ unsigned int g_count;

// max of exp(-(i-x)^2/4) over integer grid i in [0,63]: nearest grid point.
__device__ __forceinline__ float gmax1d(float x) {
    float i = fminf(fmaxf(rintf(x), 0.f), 63.f);
    float d = i - x;
    return __expf(-d * d * 0.25f);
}

__device__ __forceinline__ float blockReduce256(float v, float* red, int tid) {
    #pragma unroll
    for (int o = 16; o > 0; o >>= 1) v += __shfl_down_sync(0xffffffffu, v, o);
    if ((tid & 31) == 0) red[tid >> 5] = v;
    __syncthreads();
    v = (tid < 8) ? red[tid] : 0.f;
    if (tid < 32) {
        #pragma unroll
        for (int o = 4; o > 0; o >>= 1) v += __shfl_down_sync(0xffffffffu, v, o);
    }
    return v;   // valid on tid 0
}

__global__ void __launch_bounds__(256, 8)
k_fused(const float* __restrict__ mo,
        const float* __restrict__ joints,
        const float* __restrict__ j2d,
        const float* __restrict__ pred,
        float* __restrict__ out) {
    __shared__ __align__(16) float ex[64], ey[64], ex2[64], ey2[64];
    __shared__ float red[8];
    __shared__ int   s_last;

    const int b   = blockIdx.y;
    const int tid = threadIdx.x;

    const float4* ey4  = (const float4*)ey;
    const float4* ey24 = (const float4*)ey2;

    if (blockIdx.x < NJ) {
        // ---------------- L2D path ----------------
        const int j = blockIdx.x;
        const float x = j2d[(b * NJ + j) * 2 + 0] * 64.f;
        const float y = j2d[(b * NJ + j) * 2 + 1] * 64.f;
        const float inv = 1.f / (gmax1d(x) * gmax1d(y));
        if (tid < 64)       { float d = (float)tid - x;        ex[tid] = expf(-d * d * 0.25f) * inv; }
        else if (tid < 128) { int k = tid - 64; float d = (float)k - y; ey[k] = expf(-d * d * 0.25f); }
        __syncthreads();

        const float4* p = (const float4*)(mo + (((size_t)b * NCH + j) << 12));
        float acc = 0.f;
        #pragma unroll
        for (int it = 0; it < 4; it++) {
            int e4 = tid + it * 256;
            float4 m = p[e4];
            int i  = e4 >> 4;
            int k4 = e4 & 15;
            float  hx = ex[i];
            float4 v  = ey4[k4];
            float d0 = m.x - hx * v.x;
            float d1 = m.y - hx * v.y;
            float d2 = m.z - hx * v.z;
            float d3 = m.w - hx * v.w;
            acc += d0 * d0 + d1 * d1 + d2 * d2 + d3 * d3;
        }
        float S = blockReduce256(acc, red, tid);
        if (tid == 0) atomicAdd(&g_slot[blockIdx.x], (double)S);

        // column 0 additionally owns l3d for batch b (51 coalesced loads)
        if (j == 0) {
            float l = 0.f;
            if (tid < NJ * 3)
                l = fabsf(joints[b * NJ * 3 + tid] - pred[b * NJ * 3 + tid]);
            __syncthreads();   // red[] reuse
            float L = blockReduce256(l, red, tid);
            if (tid == 0) atomicAdd(&g_slot[GX], (double)L);
        }
    } else {
        // ---------------- HEM path ----------------
        const int pr = blockIdx.x - NJ;
        const int pj = c_par[pr], cj = c_chi[pr];
        const float xp = j2d[(b * NJ + pj) * 2 + 0] * 64.f;
        const float yp = j2d[(b * NJ + pj) * 2 + 1] * 64.f;
        const float xc = j2d[(b * NJ + cj) * 2 + 0] * 64.f;
        const float yc = j2d[(b * NJ + cj) * 2 + 1] * 64.f;
        const float invp = 1.f / (gmax1d(xp) * gmax1d(yp));
        const float invc = 1.f / (gmax1d(xc) * gmax1d(yc));
        if (tid < 64)       { float d = (float)tid - xp;         ex [tid] = expf(-d * d * 0.25f) * invp; }
        else if (tid < 128) { int k = tid - 64;  float d = (float)k - yp; ey [k] = expf(-d * d * 0.25f); }
        else if (tid < 192) { int k = tid - 128; float d = (float)k - xc; ex2[k] = expf(-d * d * 0.25f) * invc; }
        else                { int k = tid - 192; float d = (float)k - yc; ey2[k] = expf(-d * d * 0.25f); }
        __syncthreads();

        const float dz = joints[(b * NJ + pj) * 3 + 2] - joints[(b * NJ + cj) * 3 + 2];
        const int r = (dz > 0.1f) ? 1 : ((fabsf(dz) < 0.1f) ? 0 : -1);

        const float4* p0 = (const float4*)(mo + (((size_t)b * NCH + NJ + pr * 3) << 12));
        float a0 = 0.f, a1 = 0.f, a2 = 0.f;
        #pragma unroll
        for (int it = 0; it < 4; it++) {
            int e4 = tid + it * 256;
            int i  = e4 >> 4;
            int k4 = e4 & 15;
            float  hpx = ex[i];
            float  hcx = ex2[i];
            float4 vp  = ey4[k4];
            float4 vc  = ey24[k4];
            float m0[4], m1[4], m2[4];
            *(float4*)m0 = p0[e4];
            *(float4*)m1 = p0[e4 + 1024];
            *(float4*)m2 = p0[e4 + 2048];
            #pragma unroll
            for (int n = 0; n < 4; n++) {
                float hp = hpx * (&vp.x)[n];
                float hc = hcx * (&vc.x)[n];
                float t0 = (r == -1) ? hc : 0.f;
                float t1 = (r ==  0) ? (hp + hc) : hp;
                float t2 = (r ==  1) ? hc : 0.f;
                float d0 = t0 - m0[n];
                float d1 = t1 - m1[n];
                float d2 = t2 - m2[n];
                a0 += d0 * d0;
                a1 += d1 * d1;
                a2 += d2 * d2;
            }
        }
        float S0 = blockReduce256(a0, red, tid);
        __syncthreads();
        float S1 = blockReduce256(a1, red, tid);
        __syncthreads();
        float S2 = blockReduce256(a2, red, tid);
        if (tid == 0) {
            float s = sqrtf(S0) + sqrtf(S1) + sqrtf(S2);
            atomicAdd(&g_slot[blockIdx.x], (double)(s * s));
        }
    }

    // ---- last-block detection: release-ordered counter (no L1-flushing fence) ----
    if (tid == 0) {
        unsigned int prev;
        asm volatile("atom.add.release.gpu.u32 %0, [%1], 1;"
                     : "=r"(prev) : "l"(&g_count) : "memory");
        s_last = (prev == (unsigned)(NBLK - 1)) ? 1 : 0;
    }
    __syncthreads();
    if (!s_last) return;

    // ---- last block only: tiny combine + reset ----
    asm volatile("fence.acquire.gpu;" ::: "memory");
    if (tid == 0) {
        double s = 0.0;
        #pragma unroll
        for (int i = 0; i < GX; i++) s += __ldcg(&g_slot[i]);
        double l3d = __ldcg(&g_slot[GX]);
        out[0] = (float)((l3d + 0.005 * s) * (1.0 / 256.0));
        g_count = 0;
    }
    if (tid < NSLOT) g_slot[tid] = 0.0;   // reset for next graph replay
}

extern "C" void kernel_launch(void* const* d_in, const int* in_sizes, int n_in,
                              void* d_out, int out_size) {
    const float* pred   = (const float*)d_in[0];
    const float* joints = (const float*)d_in[1];
    const float* mo     = (const float*)d_in[2];
    const float* j2d    = (const float*)d_in[3];
    float* out = (float*)d_out;

    k_fused<<<dim3(GX, NB), 256>>>(mo, joints, j2d, pred, out);
}

// round 13
// speedup vs baseline: 1.2584x; 1.0442x over previous
#include <cuda_runtime.h>

#define NJ   17
#define NP   14
#define NB   256
#define NCH  59            // 17 + 3*14
#define GX   (NJ + NP)     // 31 block columns: 0..13 HEM, 14..30 L2D
#define NBLK (GX * NB)     // 7936 blocks
#define NSLOT (GX + 1)     // 31 loss slots + 1 l3d slot

__constant__ int c_par[NP] = {0,1,2,0,4,5,0,8,14,15,8,11,12,8};
__constant__ int c_chi[NP] = {1,2,3,4,5,6,8,14,15,16,11,12,13,10};

// Accumulators (L2 atomics only). Zero at module load; the last block
// re-zeroes them after reading, so every launch starts from zero.
__device__ double       g_slot[NSLOT];
__device__ unsigned int g_count;

// max of exp(-(i-x)^2/4) over integer grid i in [0,63]: nearest grid point.
__device__ __forceinline__ float gmax1d(float x) {
    float i = fminf(fmaxf(rintf(x), 0.f), 63.f);
    float d = i - x;
    return __expf(-d * d * 0.25f);
}

__device__ __forceinline__ float blockReduce256(float v, float* red, int tid) {
    #pragma unroll
    for (int o = 16; o > 0; o >>= 1) v += __shfl_down_sync(0xffffffffu, v, o);
    if ((tid & 31) == 0) red[tid >> 5] = v;
    __syncthreads();
    v = (tid < 8) ? red[tid] : 0.f;
    if (tid < 32) {
        #pragma unroll
        for (int o = 4; o > 0; o >>= 1) v += __shfl_down_sync(0xffffffffu, v, o);
    }
    return v;   // valid on tid 0
}

__global__ void __launch_bounds__(256, 8)
k_fused(const float* __restrict__ mo,
        const float* __restrict__ joints,
        const float* __restrict__ j2d,
        const float* __restrict__ pred,
        float* __restrict__ out) {
    __shared__ __align__(16) float ex[64], ey[64], ex2[64], ey2[64];
    __shared__ float red[8];
    __shared__ int   s_last;

    const int b   = blockIdx.y;
    const int tid = threadIdx.x;

    const float4* ey4  = (const float4*)ey;
    const float4* ey24 = (const float4*)ey2;

    if (blockIdx.x >= NP) {
        // ---------------- L2D path (columns 14..30 -> joints 0..16) ----------------
        const int j = blockIdx.x - NP;

        // Prefetch all 4 loads BEFORE table build: overlap DRAM latency with MUFU.
        const float4* p = (const float4*)(mo + (((size_t)b * NCH + j) << 12));
        float4 m0 = p[tid];
        float4 m1 = p[tid + 256];
        float4 m2 = p[tid + 512];
        float4 m3 = p[tid + 768];

        const float x = j2d[(b * NJ + j) * 2 + 0] * 64.f;
        const float y = j2d[(b * NJ + j) * 2 + 1] * 64.f;
        const float inv = 1.f / (gmax1d(x) * gmax1d(y));
        if (tid < 64)       { float d = (float)tid - x;        ex[tid] = expf(-d * d * 0.25f) * inv; }
        else if (tid < 128) { int k = tid - 64; float d = (float)k - y; ey[k] = expf(-d * d * 0.25f); }
        __syncthreads();

        float acc = 0.f;
        #pragma unroll
        for (int it = 0; it < 4; it++) {
            float4 m = (it == 0) ? m0 : (it == 1) ? m1 : (it == 2) ? m2 : m3;
            int e4 = tid + it * 256;
            int i  = e4 >> 4;
            int k4 = e4 & 15;
            float  hx = ex[i];
            float4 v  = ey4[k4];
            float d0 = m.x - hx * v.x;
            float d1 = m.y - hx * v.y;
            float d2 = m.z - hx * v.z;
            float d3 = m.w - hx * v.w;
            acc += d0 * d0 + d1 * d1 + d2 * d2 + d3 * d3;
        }
        float S = blockReduce256(acc, red, tid);
        if (tid == 0) atomicAdd(&g_slot[blockIdx.x], (double)S);

        // joint-0 column additionally owns l3d for batch b (51 coalesced loads)
        if (j == 0) {
            float l = 0.f;
            if (tid < NJ * 3)
                l = fabsf(joints[b * NJ * 3 + tid] - pred[b * NJ * 3 + tid]);
            __syncthreads();   // red[] reuse
            float L = blockReduce256(l, red, tid);
            if (tid == 0) atomicAdd(&g_slot[GX], (double)L);
        }
    } else {
        // ---------------- HEM path (columns 0..13 -> pairs 0..13) ----------------
        const int pr = blockIdx.x;
        const int pj = c_par[pr], cj = c_chi[pr];

        // Prefetch iteration 0's three loads before table build.
        const float4* p0 = (const float4*)(mo + (((size_t)b * NCH + NJ + pr * 3) << 12));
        float4 f0 = p0[tid];
        float4 f1 = p0[tid + 1024];
        float4 f2 = p0[tid + 2048];

        const float xp = j2d[(b * NJ + pj) * 2 + 0] * 64.f;
        const float yp = j2d[(b * NJ + pj) * 2 + 1] * 64.f;
        const float xc = j2d[(b * NJ + cj) * 2 + 0] * 64.f;
        const float yc = j2d[(b * NJ + cj) * 2 + 1] * 64.f;
        const float invp = 1.f / (gmax1d(xp) * gmax1d(yp));
        const float invc = 1.f / (gmax1d(xc) * gmax1d(yc));
        if (tid < 64)       { float d = (float)tid - xp;         ex [tid] = expf(-d * d * 0.25f) * invp; }
        else if (tid < 128) { int k = tid - 64;  float d = (float)k - yp; ey [k] = expf(-d * d * 0.25f); }
        else if (tid < 192) { int k = tid - 128; float d = (float)k - xc; ex2[k] = expf(-d * d * 0.25f) * invc; }
        else                { int k = tid - 192; float d = (float)k - yc; ey2[k] = expf(-d * d * 0.25f); }
        __syncthreads();

        const float dz = joints[(b * NJ + pj) * 3 + 2] - joints[(b * NJ + cj) * 3 + 2];
        const int r = (dz > 0.1f) ? 1 : ((fabsf(dz) < 0.1f) ? 0 : -1);

        float a0 = 0.f, a1 = 0.f, a2 = 0.f;
        #pragma unroll
        for (int it = 0; it < 4; it++) {
            int e4 = tid + it * 256;
            int i  = e4 >> 4;
            int k4 = e4 & 15;
            float  hpx = ex[i];
            float  hcx = ex2[i];
            float4 vp  = ey4[k4];
            float4 vc  = ey24[k4];
            float m0[4], m1[4], m2[4];
            if (it == 0) {
                *(float4*)m0 = f0;
                *(float4*)m1 = f1;
                *(float4*)m2 = f2;
            } else {
                *(float4*)m0 = p0[e4];
                *(float4*)m1 = p0[e4 + 1024];
                *(float4*)m2 = p0[e4 + 2048];
            }
            #pragma unroll
            for (int n = 0; n < 4; n++) {
                float hp = hpx * (&vp.x)[n];
                float hc = hcx * (&vc.x)[n];
                float t0 = (r == -1) ? hc : 0.f;
                float t1 = (r ==  0) ? (hp + hc) : hp;
                float t2 = (r ==  1) ? hc : 0.f;
                float d0 = t0 - m0[n];
                float d1 = t1 - m1[n];
                float d2 = t2 - m2[n];
                a0 += d0 * d0;
                a1 += d1 * d1;
                a2 += d2 * d2;
            }
        }
        float S0 = blockReduce256(a0, red, tid);
        __syncthreads();
        float S1 = blockReduce256(a1, red, tid);
        __syncthreads();
        float S2 = blockReduce256(a2, red, tid);
        if (tid == 0) {
            float s = sqrtf(S0) + sqrtf(S1) + sqrtf(S2);
            atomicAdd(&g_slot[blockIdx.x], (double)(s * s));
        }
    }

    // ---- last-block detection: release-ordered counter (no L1-flushing fence) ----
    if (tid == 0) {
        unsigned int prev;
        asm volatile("atom.add.release.gpu.u32 %0, [%1], 1;"
                     : "=r"(prev) : "l"(&g_count) : "memory");
        s_last = (prev == (unsigned)(NBLK - 1)) ? 1 : 0;
    }
    __syncthreads();
    if (!s_last) return;

    // ---- last block only: tiny combine + reset ----
    asm volatile("fence.acquire.gpu;" ::: "memory");
    if (tid == 0) {
        double s = 0.0;
        #pragma unroll
        for (int i = 0; i < GX; i++) s += __ldcg(&g_slot[i]);
        double l3d = __ldcg(&g_slot[GX]);
        out[0] = (float)((l3d + 0.005 * s) * (1.0 / 256.0));
        g_count = 0;
    }
    if (tid < NSLOT) g_slot[tid] = 0.0;   // reset for next graph replay
}

extern "C" void kernel_launch(void* const* d_in, const int* in_sizes, int n_in,
                              void* d_out, int out_size) {
    const float* pred   = (const float*)d_in[0];
    const float* joints = (const float*)d_in[1];
    const float* mo     = (const float*)d_in[2];
    const float* j2d    = (const float*)d_in[3];
    float* out = (float*)d_out;

    k_fused<<<dim3(GX, NB), 256>>>(mo, joints, j2d, pred, out);
}